// round 10
// baseline (speedup 1.0000x reference)
#include <cuda_runtime.h>

#define NB    4
#define NSEQ  2048
#define DIMV  512
#define NH    8
#define HD    64
#define NM    4
#define NROWS 16     // NB*NM
#define HM    32     // NH*NM
#define ASCALE 0.125f

// ---------------- scratch (device globals; no allocation allowed) ----------------
__device__ float g_q[NROWS * DIMV];
__device__ float g_qk[NB * HM * DIMV];
__device__ float g_dots[NB * HM * NSEQ];
__device__ float g_smax[NB * HM * 64];   // per-(row, 32-wide chunk) max
__device__ float g_ssum[NB * HM * 64];   // per-(row, 32-wide chunk) sum exp(v - chunkmax)
__device__ float g_ax[NB * HM * DIMV];
__device__ float g_y[NROWS * DIMV];

typedef unsigned long long u64;

__device__ __forceinline__ u64 fma2(u64 a, u64 b, u64 c) {
    u64 d; asm("fma.rn.f32x2 %0, %1, %2, %3;" : "=l"(d) : "l"(a), "l"(b), "l"(c)); return d;
}
__device__ __forceinline__ u64 pack2(float x, float y) {
    u64 r; asm("mov.b64 %0, {%1, %2};" : "=l"(r) : "f"(x), "f"(y)); return r;
}
__device__ __forceinline__ float2 unpack2(u64 v) {
    float2 f; asm("mov.b64 {%0, %1}, %2;" : "=f"(f.x), "=f"(f.y) : "l"(v)); return f;
}
__device__ __forceinline__ void redg4(float* p, float4 v) {
    asm volatile("red.global.add.v4.f32 [%0], {%1, %2, %3, %4};"
                 :: "l"(p), "f"(v.x), "f"(v.y), "f"(v.z), "f"(v.w) : "memory");
}
__device__ __forceinline__ void cpasync16(void* smem, const void* gmem) {
    unsigned saddr = (unsigned)__cvta_generic_to_shared(smem);
    asm volatile("cp.async.cg.shared.global [%0], [%1], 16;" :: "r"(saddr), "l"(gmem));
}
#define CP_COMMIT() asm volatile("cp.async.commit_group;")
#define CP_WAIT(n)  asm volatile("cp.async.wait_group %0;" :: "n"(n))

// ---------------- K1: q = x[:, 0:4] @ Wq  (16x512, k=512) ----------------
__global__ void k1_q(const float* __restrict__ x, const float* __restrict__ Wq) {
    __shared__ float A[NROWS * DIMV];
    int t = threadIdx.x;
    int c0 = blockIdx.x * 8;
    for (int i = t; i < NROWS * DIMV / 4; i += 256) {
        int r = i >> 7, k = (i & 127) << 2;
        *(float4*)&A[r * DIMV + k] =
            *(const float4*)&x[(size_t)(((r >> 2) * NSEQ) + (r & 3)) * DIMV + k];
    }
    __syncthreads();
    int cl = t & 7, kg = t >> 3;
    int c = c0 + cl;
    float acc[NROWS];
#pragma unroll
    for (int r = 0; r < NROWS; r++) acc[r] = 0.f;
    int k0 = kg << 4;
#pragma unroll
    for (int i = 0; i < 16; i++) {
        float w = Wq[(k0 + i) * DIMV + c];
#pragma unroll
        for (int r = 0; r < NROWS; r++) acc[r] += A[r * DIMV + k0 + i] * w;
    }
    __syncthreads();
#pragma unroll
    for (int r = 0; r < NROWS; r++) A[(kg << 7) + (r << 3) + cl] = acc[r];
    __syncthreads();
    if (t < 128) {
        int r = t >> 3, c2 = t & 7;
        float s = 0.f;
#pragma unroll
        for (int kg2 = 0; kg2 < 32; kg2++) s += A[(kg2 << 7) + (r << 3) + c2];
        g_q[r * DIMV + c0 + c2] = s;
    }
}

// ---------------- K2: qk + zero g_ax ----------------
__global__ void k2_qk(const float* __restrict__ Wkv) {
    __shared__ float Ws[32][68];
    __shared__ float Qs[16][68];
    int t = threadIdx.x;
    int h = blockIdx.x >> 4, kc = blockIdx.x & 15;
    int kin0 = kc << 5;
#pragma unroll
    for (int i = 0; i < 2; i++) {
        int idx = t + (i << 8);
        int r = idx >> 4, c = (idx & 15) << 2;
        *(float4*)&Ws[r][c] =
            *(const float4*)&Wkv[(size_t)(kin0 + r) * (2 * DIMV) + h * HD + c];
    }
    {
        int r = t >> 4, c = (t & 15) << 2;
        *(float4*)&Qs[r][c] = *(const float4*)&g_q[r * DIMV + h * HD + c];
    }
    __syncthreads();
    int bm = t >> 4, kin = t & 15;
    float acc0 = 0.f, acc1 = 0.f;
#pragma unroll
    for (int dd = 0; dd < HD; dd += 4) {
        float4 q  = *(const float4*)&Qs[bm][dd];
        float4 w0 = *(const float4*)&Ws[kin][dd];
        float4 w1 = *(const float4*)&Ws[kin + 16][dd];
        acc0 += q.x * w0.x + q.y * w0.y + q.z * w0.z + q.w * w0.w;
        acc1 += q.x * w1.x + q.y * w1.y + q.z * w1.z + q.w * w1.w;
    }
    int b = bm >> 2, m = bm & 3;
    int hm = (h << 2) + m;
    g_qk[(b * HM + hm) * DIMV + kin0 + kin] = acc0;
    g_qk[(b * HM + hm) * DIMV + kin0 + kin + 16] = acc1;
    int zi = blockIdx.x * 256 + t;
    g_ax[zi] = 0.f;
    g_ax[zi + 32768] = 0.f;
}

// ---------------- K3: dots = qk @ x^T * SCALE + bias + chunk stats ----------------
// grid 256 = (b, n-chunk 32). 256 thr: 32 hm x 8 tn, 1hm x 4n per thread.
// X double-buffered + register-pipelined LDG; QK single-buffered. smem ~27 KB.
__global__ void k3_dots(const float* __restrict__ x, const float* __restrict__ bias) {
    __shared__ float QKs[64][34];       // [kk][hm]  (136 B rows: float-safe)
    __shared__ float Xs[2][64][36];     // [kk][nn]  (144 B rows: 16B-aligned slots)
    int t = threadIdx.x;
    int b = blockIdx.x >> 6, nb = blockIdx.x & 63;
    int n0 = nb << 5;
    int tn = t & 7, hm = t >> 3;
    int n4 = tn << 2;
    // loader mapping: both QK and X use 32 rows x 8 quads, 2 float4 each
    int l_row = t >> 3, l_q8 = t & 7;
    float4 qv[2], xv[2];

    u64 acc0 = pack2(0.f, 0.f), acc1 = pack2(0.f, 0.f);

#define K3_LDG(dt)                                                                        \
    {   int d0_ = (dt) << 6;                                                              \
        _Pragma("unroll")                                                                 \
        for (int i = 0; i < 2; i++)                                                       \
            qv[i] = *(const float4*)&g_qk[(b * HM + l_row) * DIMV + d0_ + ((l_q8 + (i << 3)) << 2)]; \
        _Pragma("unroll")                                                                 \
        for (int i = 0; i < 2; i++)                                                       \
            xv[i] = *(const float4*)&x[(size_t)(b * NSEQ + n0 + l_row) * DIMV + d0_ + ((l_q8 + (i << 3)) << 2)]; \
    }
#define K3_STS_QK()                                                                       \
    {   _Pragma("unroll")                                                                 \
        for (int i = 0; i < 2; i++) {                                                     \
            int kk = (l_q8 + (i << 3)) << 2;                                              \
            QKs[kk][l_row] = qv[i].x; QKs[kk + 1][l_row] = qv[i].y;                       \
            QKs[kk + 2][l_row] = qv[i].z; QKs[kk + 3][l_row] = qv[i].w;                   \
        }                                                                                 \
    }
#define K3_STS_X(buf)                                                                     \
    {   _Pragma("unroll")                                                                 \
        for (int i = 0; i < 2; i++) {                                                     \
            int kk = (l_q8 + (i << 3)) << 2;                                              \
            Xs[buf][kk][l_row] = xv[i].x; Xs[buf][kk + 1][l_row] = xv[i].y;               \
            Xs[buf][kk + 2][l_row] = xv[i].z; Xs[buf][kk + 3][l_row] = xv[i].w;           \
        }                                                                                 \
    }

    K3_LDG(0); K3_STS_QK(); K3_STS_X(0);
    K3_LDG(1);
    __syncthreads();
    for (int dt = 0; dt < 8; dt++) {
        int buf = dt & 1;
#pragma unroll
        for (int kk = 0; kk < 64; kk++) {
            float a = QKs[kk][hm];
            ulonglong2 xx = *(const ulonglong2*)&Xs[buf][kk][n4];
            u64 a0 = pack2(a, a);
            acc0 = fma2(a0, xx.x, acc0);
            acc1 = fma2(a0, xx.y, acc1);
        }
        __syncthreads();
        if (dt < 7) {
            K3_STS_QK();               // dt+1's QK (single buffer, post-barrier)
            K3_STS_X(1 - buf);         // dt+1's X
            if (dt + 2 < 8) K3_LDG(dt + 2);
            __syncthreads();
        }
    }
    // epilogue: bias add, store, 32-wide chunk stats
    {
        int h = hm >> 2, m = hm & 3;
        float4 bv = *(const float4*)&bias[(size_t)((b * NH + h) * NSEQ + m) * NSEQ + n0 + n4];
        float2 p0 = unpack2(acc0);
        float2 p1 = unpack2(acc1);
        float4 o = make_float4(p0.x * ASCALE + bv.x, p0.y * ASCALE + bv.y,
                               p1.x * ASCALE + bv.z, p1.y * ASCALE + bv.w);
        *(float4*)&g_dots[(b * HM + hm) * NSEQ + n0 + n4] = o;
        float M = fmaxf(fmaxf(o.x, o.y), fmaxf(o.z, o.w));
#pragma unroll
        for (int off = 4; off; off >>= 1) M = fmaxf(M, __shfl_xor_sync(0xffffffffu, M, off));
        float s = __expf(o.x - M) + __expf(o.y - M) + __expf(o.z - M) + __expf(o.w - M);
#pragma unroll
        for (int off = 4; off; off >>= 1) s += __shfl_xor_sync(0xffffffffu, s, off);
        if (tn == 0) {
            g_smax[(b * HM + hm) * 64 + nb] = M;
            g_ssum[(b * HM + hm) * 64 + nb] = s;
        }
    }
}

// ---------------- K5: ax += softmax(dots) @ x  (cp.async pipelined, REDG accumulate) ----------------
// grid 256 = (b, n-chunk 64 idx 0..31, d-half 0..1). 256 thr. 4 sub-tiles 16n x 256d, 2 buffers.
__global__ void k5_part(const float* __restrict__ x) {
    __shared__ float As[64][36];
    __shared__ __align__(16) float Xs[2][16][264];
    __shared__ float sM[32], sInv[32];
    int t = threadIdx.x;
    int b = blockIdx.x >> 6;
    int rest = blockIdx.x & 63;
    int nc = rest >> 1, dh = rest & 1;
    int n0 = nc << 6, d0 = dh << 8;
    int td = t & 31, thm = t >> 5;
    int hm4 = thm << 2;
    // cp.async loader mapping: 16 rows x 64 float4, 256 thr -> 4 copies each
    int c_nn = t >> 4, c_q16 = t & 15;

#define K5_ISSUE(s, buf)                                                                  \
    {   const float* gsrc = &x[(size_t)(b * NSEQ + n0 + ((s) << 4) + c_nn) * DIMV + d0];  \
        _Pragma("unroll")                                                                 \
        for (int i = 0; i < 4; i++) {                                                     \
            int dd = (c_q16 + (i << 4)) << 2;                                             \
            cpasync16(&Xs[buf][c_nn][dd], gsrc + dd);                                     \
        }                                                                                 \
        CP_COMMIT();                                                                      \
    }

    K5_ISSUE(0, 0);
    K5_ISSUE(1, 1);
    // stats prologue: combine 64 chunk stats per row -> row max M and 1/S
    {
        int row = t >> 3, j8 = t & 7;
        const float* pm = g_smax + (b * HM + row) * 64 + (j8 << 3);
        const float* ps = g_ssum + (b * HM + row) * 64 + (j8 << 3);
        float mv[8], sv[8];
        float M = -3.4e38f;
#pragma unroll
        for (int i = 0; i < 8; i++) { mv[i] = pm[i]; sv[i] = ps[i]; M = fmaxf(M, mv[i]); }
#pragma unroll
        for (int off = 4; off; off >>= 1) M = fmaxf(M, __shfl_xor_sync(0xffffffffu, M, off));
        float s = 0.f;
#pragma unroll
        for (int i = 0; i < 8; i++) s += __expf(mv[i] - M) * sv[i];
#pragma unroll
        for (int off = 4; off; off >>= 1) s += __shfl_xor_sync(0xffffffffu, s, off);
        if (j8 == 0) { sM[row] = M; sInv[row] = 1.f / s; }
    }
    __syncthreads();
    // As: 64n x 32hm transposed, exp applied (overlaps async loads)
    {
        int hm = t >> 3, q8 = t & 7;
        float M = sM[hm], is = sInv[hm];
#pragma unroll
        for (int i = 0; i < 2; i++) {
            int nn = (q8 + (i << 3)) << 2;
            float4 v = *(const float4*)&g_dots[(b * HM + hm) * NSEQ + n0 + nn];
            As[nn][hm]     = __expf(v.x - M) * is;
            As[nn + 1][hm] = __expf(v.y - M) * is;
            As[nn + 2][hm] = __expf(v.z - M) * is;
            As[nn + 3][hm] = __expf(v.w - M) * is;
        }
    }
    u64 acc[4][4];
#pragma unroll
    for (int j = 0; j < 4; j++)
#pragma unroll
        for (int k = 0; k < 4; k++) acc[j][k] = pack2(0.f, 0.f);

    for (int s = 0; s < 4; s++) {
        if (s < 3) { CP_WAIT(1); } else { CP_WAIT(0); }
        __syncthreads();
        int buf = s & 1;
#pragma unroll
        for (int nn2 = 0; nn2 < 16; nn2++) {
            float4 a = *(const float4*)&As[(s << 4) + nn2][hm4];           // warp broadcast
            ulonglong2 x0 = *(const ulonglong2*)&Xs[buf][nn2][td << 2];
            ulonglong2 x1 = *(const ulonglong2*)&Xs[buf][nn2][128 + (td << 2)];
            u64 a0 = pack2(a.x, a.x), a1 = pack2(a.y, a.y);
            u64 a2 = pack2(a.z, a.z), a3 = pack2(a.w, a.w);
            acc[0][0] = fma2(a0, x0.x, acc[0][0]); acc[0][1] = fma2(a0, x0.y, acc[0][1]);
            acc[0][2] = fma2(a0, x1.x, acc[0][2]); acc[0][3] = fma2(a0, x1.y, acc[0][3]);
            acc[1][0] = fma2(a1, x0.x, acc[1][0]); acc[1][1] = fma2(a1, x0.y, acc[1][1]);
            acc[1][2] = fma2(a1, x1.x, acc[1][2]); acc[1][3] = fma2(a1, x1.y, acc[1][3]);
            acc[2][0] = fma2(a2, x0.x, acc[2][0]); acc[2][1] = fma2(a2, x0.y, acc[2][1]);
            acc[2][2] = fma2(a2, x1.x, acc[2][2]); acc[2][3] = fma2(a2, x1.y, acc[2][3]);
            acc[3][0] = fma2(a3, x0.x, acc[3][0]); acc[3][1] = fma2(a3, x0.y, acc[3][1]);
            acc[3][2] = fma2(a3, x1.x, acc[3][2]); acc[3][3] = fma2(a3, x1.y, acc[3][3]);
        }
        __syncthreads();
        if (s + 2 < 4) { K5_ISSUE(s + 2, buf); }
    }
#pragma unroll
    for (int j = 0; j < 4; j++) {
        float* base = &g_ax[(size_t)(b * HM + hm4 + j) * DIMV + d0];
        float2 p0 = unpack2(acc[j][0]), p1 = unpack2(acc[j][1]);
        redg4(base + (td << 2), make_float4(p0.x, p0.y, p1.x, p1.y));
        float2 p2 = unpack2(acc[j][2]), p3 = unpack2(acc[j][3]);
        redg4(base + 128 + (td << 2), make_float4(p2.x, p2.y, p3.x, p3.y));
    }
}

// ---------------- K7: y[:, c] = ax_h @ Wv[:, c], h = c/64 ----------------
__global__ void k7_y(const float* __restrict__ Wkv) {
    __shared__ float A[NROWS * DIMV];
    int t = threadIdx.x;
    int c0 = blockIdx.x * 8;
    int h = c0 >> 6;
    for (int i = t; i < NROWS * DIMV / 4; i += 256) {
        int r = i >> 7, k = (i & 127) << 2;
        *(float4*)&A[r * DIMV + k] =
            *(const float4*)&g_ax[(size_t)((((r >> 2) * NH + h) * NM) + (r & 3)) * DIMV + k];
    }
    __syncthreads();
    int cl = t & 7, kg = t >> 3;
    int c = c0 + cl;
    float acc[NROWS];
#pragma unroll
    for (int r = 0; r < NROWS; r++) acc[r] = 0.f;
    int k0 = kg << 4;
#pragma unroll
    for (int i = 0; i < 16; i++) {
        float w = Wkv[(size_t)(k0 + i) * (2 * DIMV) + DIMV + c];
#pragma unroll
        for (int r = 0; r < NROWS; r++) acc[r] += A[r * DIMV + k0 + i] * w;
    }
    __syncthreads();
#pragma unroll
    for (int r = 0; r < NROWS; r++) A[(kg << 7) + (r << 3) + cl] = acc[r];
    __syncthreads();
    if (t < 128) {
        int r = t >> 3, c2 = t & 7;
        float s = 0.f;
#pragma unroll
        for (int kg2 = 0; kg2 < 32; kg2++) s += A[(kg2 << 7) + (r << 3) + c2];
        g_y[r * DIMV + c0 + c2] = s;
    }
}

// ---------------- K8: out = y @ Wo + bo ----------------
__global__ void k8_out(const float* __restrict__ Wo, const float* __restrict__ bo,
                       float* __restrict__ out) {
    __shared__ float A[NROWS * DIMV];
    int t = threadIdx.x;
    int c0 = blockIdx.x * 8;
    for (int i = t; i < NROWS * DIMV / 4; i += 256)
        *(float4*)&A[i << 2] = *(const float4*)&g_y[i << 2];
    __syncthreads();
    int cl = t & 7, kg = t >> 3;
    int c = c0 + cl;
    float acc[NROWS];
#pragma unroll
    for (int r = 0; r < NROWS; r++) acc[r] = 0.f;
    int k0 = kg << 4;
#pragma unroll
    for (int i = 0; i < 16; i++) {
        float w = Wo[(k0 + i) * DIMV + c];
#pragma unroll
        for (int r = 0; r < NROWS; r++) acc[r] += A[r * DIMV + k0 + i] * w;
    }
    __syncthreads();
#pragma unroll
    for (int r = 0; r < NROWS; r++) A[(kg << 7) + (r << 3) + cl] = acc[r];
    __syncthreads();
    if (t < 128) {
        int r = t >> 3, c2 = t & 7;
        float s = 0.f;
#pragma unroll
        for (int kg2 = 0; kg2 < 32; kg2++) s += A[(kg2 << 7) + (r << 3) + c2];
        out[r * DIMV + c0 + c2] = s + bo[c0 + c2];
    }
}

// ---------------- launch ----------------
extern "C" void kernel_launch(void* const* d_in, const int* in_sizes, int n_in,
                              void* d_out, int out_size) {
    const float* x    = (const float*)d_in[0];   // (4, 2048, 512)
    const float* bias = (const float*)d_in[1];   // (4, 8, 2048, 2048)
    const float* Wq   = (const float*)d_in[2];   // (512, 512)
    const float* Wkv  = (const float*)d_in[3];   // (512, 1024)
    const float* Wo   = (const float*)d_in[4];   // (512, 512)
    const float* bo   = (const float*)d_in[5];   // (512,)
    float* out = (float*)d_out;                  // (4, 4, 512)

    k1_q<<<64, 256>>>(x, Wq);
    k2_qk<<<128, 256>>>(Wkv);
    k3_dots<<<256, 256>>>(x, bias);
    k5_part<<<256, 256>>>(x);
    k7_y<<<64, 256>>>(Wkv);
    k8_out<<<64, 256>>>(Wo, bo, out);
}

// round 11
// speedup vs baseline: 1.2159x; 1.2159x over previous
#include <cuda_runtime.h>

#define NB    4
#define NSEQ  2048
#define DIMV  512
#define NH    8
#define HD    64
#define NM    4
#define NROWS 16     // NB*NM
#define HM    32     // NH*NM
#define ASCALE 0.125f

// ---------------- scratch (device globals; no allocation allowed) ----------------
__device__ float g_q[NROWS * DIMV];
__device__ float g_qk[NB * HM * DIMV];
__device__ float g_dots[NB * HM * NSEQ];
__device__ float g_smax[NB * HM * 32];   // per-(row, 64-wide chunk) max
__device__ float g_ssum[NB * HM * 32];   // per-(row, 64-wide chunk) sum exp(v - chunkmax)
__device__ float g_ax[NB * HM * DIMV];
__device__ float g_y[NROWS * DIMV];

typedef unsigned long long u64;

__device__ __forceinline__ u64 fma2(u64 a, u64 b, u64 c) {
    u64 d; asm("fma.rn.f32x2 %0, %1, %2, %3;" : "=l"(d) : "l"(a), "l"(b), "l"(c)); return d;
}
__device__ __forceinline__ u64 pack2(float x, float y) {
    u64 r; asm("mov.b64 %0, {%1, %2};" : "=l"(r) : "f"(x), "f"(y)); return r;
}
__device__ __forceinline__ float2 unpack2(u64 v) {
    float2 f; asm("mov.b64 {%0, %1}, %2;" : "=f"(f.x), "=f"(f.y) : "l"(v)); return f;
}
__device__ __forceinline__ void redg4(float* p, float4 v) {
    asm volatile("red.global.add.v4.f32 [%0], {%1, %2, %3, %4};"
                 :: "l"(p), "f"(v.x), "f"(v.y), "f"(v.z), "f"(v.w) : "memory");
}
__device__ __forceinline__ void cpasync16(void* smem, const void* gmem) {
    unsigned saddr = (unsigned)__cvta_generic_to_shared(smem);
    asm volatile("cp.async.cg.shared.global [%0], [%1], 16;" :: "r"(saddr), "l"(gmem));
}
#define CP_COMMIT() asm volatile("cp.async.commit_group;")
#define CP_WAIT(n)  asm volatile("cp.async.wait_group %0;" :: "n"(n))

// ---------------- K1: q = x[:, 0:4] @ Wq  (16x512, k=512) ----------------
__global__ void k1_q(const float* __restrict__ x, const float* __restrict__ Wq) {
    __shared__ float A[NROWS * DIMV];
    int t = threadIdx.x;
    int c0 = blockIdx.x * 8;
    for (int i = t; i < NROWS * DIMV / 4; i += 256) {
        int r = i >> 7, k = (i & 127) << 2;
        *(float4*)&A[r * DIMV + k] =
            *(const float4*)&x[(size_t)(((r >> 2) * NSEQ) + (r & 3)) * DIMV + k];
    }
    __syncthreads();
    int cl = t & 7, kg = t >> 3;
    int c = c0 + cl;
    float acc[NROWS];
#pragma unroll
    for (int r = 0; r < NROWS; r++) acc[r] = 0.f;
    int k0 = kg << 4;
#pragma unroll
    for (int i = 0; i < 16; i++) {
        float w = Wq[(k0 + i) * DIMV + c];
#pragma unroll
        for (int r = 0; r < NROWS; r++) acc[r] += A[r * DIMV + k0 + i] * w;
    }
    __syncthreads();
#pragma unroll
    for (int r = 0; r < NROWS; r++) A[(kg << 7) + (r << 3) + cl] = acc[r];
    __syncthreads();
    if (t < 128) {
        int r = t >> 3, c2 = t & 7;
        float s = 0.f;
#pragma unroll
        for (int kg2 = 0; kg2 < 32; kg2++) s += A[(kg2 << 7) + (r << 3) + c2];
        g_q[r * DIMV + c0 + c2] = s;
    }
}

// ---------------- K2: qk + zero g_ax ----------------
__global__ void k2_qk(const float* __restrict__ Wkv) {
    __shared__ float Ws[32][68];
    __shared__ float Qs[16][68];
    int t = threadIdx.x;
    int h = blockIdx.x >> 4, kc = blockIdx.x & 15;
    int kin0 = kc << 5;
#pragma unroll
    for (int i = 0; i < 2; i++) {
        int idx = t + (i << 8);
        int r = idx >> 4, c = (idx & 15) << 2;
        *(float4*)&Ws[r][c] =
            *(const float4*)&Wkv[(size_t)(kin0 + r) * (2 * DIMV) + h * HD + c];
    }
    {
        int r = t >> 4, c = (t & 15) << 2;
        *(float4*)&Qs[r][c] = *(const float4*)&g_q[r * DIMV + h * HD + c];
    }
    __syncthreads();
    int bm = t >> 4, kin = t & 15;
    float acc0 = 0.f, acc1 = 0.f;
#pragma unroll
    for (int dd = 0; dd < HD; dd += 4) {
        float4 q  = *(const float4*)&Qs[bm][dd];
        float4 w0 = *(const float4*)&Ws[kin][dd];
        float4 w1 = *(const float4*)&Ws[kin + 16][dd];
        acc0 += q.x * w0.x + q.y * w0.y + q.z * w0.z + q.w * w0.w;
        acc1 += q.x * w1.x + q.y * w1.y + q.z * w1.z + q.w * w1.w;
    }
    int b = bm >> 2, m = bm & 3;
    int hm = (h << 2) + m;
    g_qk[(b * HM + hm) * DIMV + kin0 + kin] = acc0;
    g_qk[(b * HM + hm) * DIMV + kin0 + kin + 16] = acc1;
    int zi = blockIdx.x * 256 + t;
    g_ax[zi] = 0.f;
    g_ax[zi + 32768] = 0.f;
}

// ---------------- K3: dots = qk @ x^T * SCALE + bias + chunk stats (R9 version) ----------------
// grid 128 = (b, n-chunk 64). 256 thr. X double-buffered + register-pipelined LDG.
__global__ void k3_dots(const float* __restrict__ x, const float* __restrict__ bias) {
    __shared__ float QKs[64][34];
    __shared__ float Xs[2][64][68];
    int t = threadIdx.x;
    int b = blockIdx.x >> 5, nb = blockIdx.x & 31;
    int n0 = nb << 6;
    int tn = t & 15, th = t >> 4;
    int n4 = tn << 2, hm2 = th << 1;
    int l_hm = t >> 3, l_q8 = t & 7;
    int l_nn = t >> 2, l_q4 = t & 3;
    float4 qv[2], xv[4];

    u64 acc[2][2];
#pragma unroll
    for (int j = 0; j < 2; j++) { acc[j][0] = pack2(0.f, 0.f); acc[j][1] = pack2(0.f, 0.f); }

#define K3_LDG(dt)                                                                        \
    {   int d0_ = (dt) << 6;                                                              \
        _Pragma("unroll")                                                                 \
        for (int i = 0; i < 2; i++)                                                       \
            qv[i] = *(const float4*)&g_qk[(b * HM + l_hm) * DIMV + d0_ + ((l_q8 + (i << 3)) << 2)]; \
        _Pragma("unroll")                                                                 \
        for (int i = 0; i < 4; i++)                                                       \
            xv[i] = *(const float4*)&x[(size_t)(b * NSEQ + n0 + l_nn) * DIMV + d0_ + ((l_q4 + (i << 2)) << 2)]; \
    }
#define K3_STS_QK()                                                                       \
    {   _Pragma("unroll")                                                                 \
        for (int i = 0; i < 2; i++) {                                                     \
            int kk = (l_q8 + (i << 3)) << 2;                                              \
            QKs[kk][l_hm] = qv[i].x; QKs[kk + 1][l_hm] = qv[i].y;                         \
            QKs[kk + 2][l_hm] = qv[i].z; QKs[kk + 3][l_hm] = qv[i].w;                     \
        }                                                                                 \
    }
#define K3_STS_X(buf)                                                                     \
    {   _Pragma("unroll")                                                                 \
        for (int i = 0; i < 4; i++) {                                                     \
            int kk = (l_q4 + (i << 2)) << 2;                                              \
            Xs[buf][kk][l_nn] = xv[i].x; Xs[buf][kk + 1][l_nn] = xv[i].y;                 \
            Xs[buf][kk + 2][l_nn] = xv[i].z; Xs[buf][kk + 3][l_nn] = xv[i].w;             \
        }                                                                                 \
    }

    K3_LDG(0); K3_STS_QK(); K3_STS_X(0);
    K3_LDG(1);
    __syncthreads();
    for (int dt = 0; dt < 8; dt++) {
        int buf = dt & 1;
#pragma unroll
        for (int kk = 0; kk < 64; kk++) {
            float2 a = *(const float2*)&QKs[kk][hm2];
            ulonglong2 xx = *(const ulonglong2*)&Xs[buf][kk][n4];
            u64 a0 = pack2(a.x, a.x), a1 = pack2(a.y, a.y);
            acc[0][0] = fma2(a0, xx.x, acc[0][0]);
            acc[0][1] = fma2(a0, xx.y, acc[0][1]);
            acc[1][0] = fma2(a1, xx.x, acc[1][0]);
            acc[1][1] = fma2(a1, xx.y, acc[1][1]);
        }
        __syncthreads();
        if (dt < 7) {
            K3_STS_QK();
            K3_STS_X(1 - buf);
            if (dt + 2 < 8) K3_LDG(dt + 2);
            __syncthreads();
        }
    }
#pragma unroll
    for (int j = 0; j < 2; j++) {
        int hm = hm2 + j;
        int h = hm >> 2, m = hm & 3;
        float4 bv = *(const float4*)&bias[(size_t)((b * NH + h) * NSEQ + m) * NSEQ + n0 + n4];
        float2 p0 = unpack2(acc[j][0]);
        float2 p1 = unpack2(acc[j][1]);
        float4 o = make_float4(p0.x * ASCALE + bv.x, p0.y * ASCALE + bv.y,
                               p1.x * ASCALE + bv.z, p1.y * ASCALE + bv.w);
        *(float4*)&g_dots[(b * HM + hm) * NSEQ + n0 + n4] = o;
        float M = fmaxf(fmaxf(o.x, o.y), fmaxf(o.z, o.w));
#pragma unroll
        for (int off = 8; off; off >>= 1) M = fmaxf(M, __shfl_xor_sync(0xffffffffu, M, off));
        float s = __expf(o.x - M) + __expf(o.y - M) + __expf(o.z - M) + __expf(o.w - M);
#pragma unroll
        for (int off = 8; off; off >>= 1) s += __shfl_xor_sync(0xffffffffu, s, off);
        if (tn == 0) {
            g_smax[(b * HM + hm) * 32 + nb] = M;
            g_ssum[(b * HM + hm) * 32 + nb] = s;
        }
    }
}

// ---------------- K5: ax += softmax(dots) @ x  (full-d blocks, cp.async x8, REDG) ----------------
// grid 128 = (b, n-chunk 64 idx 0..31). 512 thr: 16 warps = 8 hm-groups x 2 d-halves.
// Per thread: 4hm x 8d register tile. 8 sub-tiles of 8n x 512d, 2 buffers.
__global__ void __launch_bounds__(512) k5_part(const float* __restrict__ x) {
    __shared__ float As[64][36];
    __shared__ __align__(16) float Xs[2][8][520];   // 520-fl rows: 2080 B, 16B-aligned slots
    __shared__ float sM[32], sInv[32];
    int t = threadIdx.x;
    int b = blockIdx.x >> 5, nc = blockIdx.x & 31;
    int n0 = nc << 6;
    int td = t & 31, wid = t >> 5;
    int hm4 = (wid & 7) << 2;
    int dbase = (wid >> 3) << 8;       // 0 or 256
    // cp.async loader: 8 rows x 128 float4 per stage, 512 thr -> 2 each
    int c_nn = t >> 6, c_q = t & 63;

#define K5_ISSUE(s, buf)                                                                  \
    {   const float* gsrc = &x[(size_t)(b * NSEQ + n0 + ((s) << 3) + c_nn) * DIMV];       \
        _Pragma("unroll")                                                                 \
        for (int i = 0; i < 2; i++) {                                                     \
            int dd = (c_q + (i << 6)) << 2;                                               \
            cpasync16(&Xs[buf][c_nn][dd], gsrc + dd);                                     \
        }                                                                                 \
        CP_COMMIT();                                                                      \
    }

    K5_ISSUE(0, 0);
    K5_ISSUE(1, 1);
    // stats prologue: combine 32 chunk stats per row (overlaps async loads)
    if (t < 256) {
        int row = t >> 3, j8 = t & 7;
        const float* pm = g_smax + (b * HM + row) * 32 + (j8 << 2);
        const float* ps = g_ssum + (b * HM + row) * 32 + (j8 << 2);
        float mv[4], sv[4];
        float M = -3.4e38f;
#pragma unroll
        for (int i = 0; i < 4; i++) { mv[i] = pm[i]; sv[i] = ps[i]; M = fmaxf(M, mv[i]); }
#pragma unroll
        for (int off = 4; off; off >>= 1) M = fmaxf(M, __shfl_xor_sync(0xffffffffu, M, off));
        float s = 0.f;
#pragma unroll
        for (int i = 0; i < 4; i++) s += __expf(mv[i] - M) * sv[i];
#pragma unroll
        for (int off = 4; off; off >>= 1) s += __shfl_xor_sync(0xffffffffu, s, off);
        if (j8 == 0) { sM[row] = M; sInv[row] = 1.f / s; }
    }
    __syncthreads();
    // As: 64n x 32hm transposed, exp applied; 512 thr -> 1 float4 each
    {
        int hm = t >> 4, q16 = t & 15;
        float M = sM[hm], is = sInv[hm];
        int nn = q16 << 2;
        float4 v = *(const float4*)&g_dots[(b * HM + hm) * NSEQ + n0 + nn];
        As[nn][hm]     = __expf(v.x - M) * is;
        As[nn + 1][hm] = __expf(v.y - M) * is;
        As[nn + 2][hm] = __expf(v.z - M) * is;
        As[nn + 3][hm] = __expf(v.w - M) * is;
    }
    u64 acc[4][4];
#pragma unroll
    for (int j = 0; j < 4; j++)
#pragma unroll
        for (int k = 0; k < 4; k++) acc[j][k] = pack2(0.f, 0.f);

    for (int s = 0; s < 8; s++) {
        if (s < 7) { CP_WAIT(1); } else { CP_WAIT(0); }
        __syncthreads();
        int buf = s & 1;
#pragma unroll
        for (int nn2 = 0; nn2 < 8; nn2++) {
            float4 a = *(const float4*)&As[(s << 3) + nn2][hm4];             // warp broadcast
            ulonglong2 x0 = *(const ulonglong2*)&Xs[buf][nn2][dbase + (td << 2)];
            ulonglong2 x1 = *(const ulonglong2*)&Xs[buf][nn2][dbase + 128 + (td << 2)];
            u64 a0 = pack2(a.x, a.x), a1 = pack2(a.y, a.y);
            u64 a2 = pack2(a.z, a.z), a3 = pack2(a.w, a.w);
            acc[0][0] = fma2(a0, x0.x, acc[0][0]); acc[0][1] = fma2(a0, x0.y, acc[0][1]);
            acc[0][2] = fma2(a0, x1.x, acc[0][2]); acc[0][3] = fma2(a0, x1.y, acc[0][3]);
            acc[1][0] = fma2(a1, x0.x, acc[1][0]); acc[1][1] = fma2(a1, x0.y, acc[1][1]);
            acc[1][2] = fma2(a1, x1.x, acc[1][2]); acc[1][3] = fma2(a1, x1.y, acc[1][3]);
            acc[2][0] = fma2(a2, x0.x, acc[2][0]); acc[2][1] = fma2(a2, x0.y, acc[2][1]);
            acc[2][2] = fma2(a2, x1.x, acc[2][2]); acc[2][3] = fma2(a2, x1.y, acc[2][3]);
            acc[3][0] = fma2(a3, x0.x, acc[3][0]); acc[3][1] = fma2(a3, x0.y, acc[3][1]);
            acc[3][2] = fma2(a3, x1.x, acc[3][2]); acc[3][3] = fma2(a3, x1.y, acc[3][3]);
        }
        __syncthreads();
        if (s + 2 < 8) { K5_ISSUE(s + 2, buf); }
    }
#pragma unroll
    for (int j = 0; j < 4; j++) {
        float* base = &g_ax[(size_t)(b * HM + hm4 + j) * DIMV + dbase];
        float2 p0 = unpack2(acc[j][0]), p1 = unpack2(acc[j][1]);
        redg4(base + (td << 2), make_float4(p0.x, p0.y, p1.x, p1.y));
        float2 p2 = unpack2(acc[j][2]), p3 = unpack2(acc[j][3]);
        redg4(base + 128 + (td << 2), make_float4(p2.x, p2.y, p3.x, p3.y));
    }
}

// ---------------- K7: y[:, c] = ax_h @ Wv[:, c], h = c/64 ----------------
__global__ void k7_y(const float* __restrict__ Wkv) {
    __shared__ float A[NROWS * DIMV];
    int t = threadIdx.x;
    int c0 = blockIdx.x * 8;
    int h = c0 >> 6;
    for (int i = t; i < NROWS * DIMV / 4; i += 256) {
        int r = i >> 7, k = (i & 127) << 2;
        *(float4*)&A[r * DIMV + k] =
            *(const float4*)&g_ax[(size_t)((((r >> 2) * NH + h) * NM) + (r & 3)) * DIMV + k];
    }
    __syncthreads();
    int cl = t & 7, kg = t >> 3;
    int c = c0 + cl;
    float acc[NROWS];
#pragma unroll
    for (int r = 0; r < NROWS; r++) acc[r] = 0.f;
    int k0 = kg << 4;
#pragma unroll
    for (int i = 0; i < 16; i++) {
        float w = Wkv[(size_t)(k0 + i) * (2 * DIMV) + DIMV + c];
#pragma unroll
        for (int r = 0; r < NROWS; r++) acc[r] += A[r * DIMV + k0 + i] * w;
    }
    __syncthreads();
#pragma unroll
    for (int r = 0; r < NROWS; r++) A[(kg << 7) + (r << 3) + cl] = acc[r];
    __syncthreads();
    if (t < 128) {
        int r = t >> 3, c2 = t & 7;
        float s = 0.f;
#pragma unroll
        for (int kg2 = 0; kg2 < 32; kg2++) s += A[(kg2 << 7) + (r << 3) + c2];
        g_y[r * DIMV + c0 + c2] = s;
    }
}

// ---------------- K8: out = y @ Wo + bo ----------------
__global__ void k8_out(const float* __restrict__ Wo, const float* __restrict__ bo,
                       float* __restrict__ out) {
    __shared__ float A[NROWS * DIMV];
    int t = threadIdx.x;
    int c0 = blockIdx.x * 8;
    for (int i = t; i < NROWS * DIMV / 4; i += 256)
        *(float4*)&A[i << 2] = *(const float4*)&g_y[i << 2];
    __syncthreads();
    int cl = t & 7, kg = t >> 3;
    int c = c0 + cl;
    float acc[NROWS];
#pragma unroll
    for (int r = 0; r < NROWS; r++) acc[r] = 0.f;
    int k0 = kg << 4;
#pragma unroll
    for (int i = 0; i < 16; i++) {
        float w = Wo[(k0 + i) * DIMV + c];
#pragma unroll
        for (int r = 0; r < NROWS; r++) acc[r] += A[r * DIMV + k0 + i] * w;
    }
    __syncthreads();
#pragma unroll
    for (int r = 0; r < NROWS; r++) A[(kg << 7) + (r << 3) + cl] = acc[r];
    __syncthreads();
    if (t < 128) {
        int r = t >> 3, c2 = t & 7;
        float s = 0.f;
#pragma unroll
        for (int kg2 = 0; kg2 < 32; kg2++) s += A[(kg2 << 7) + (r << 3) + c2];
        out[r * DIMV + c0 + c2] = s + bo[c0 + c2];
    }
}

// ---------------- launch ----------------
extern "C" void kernel_launch(void* const* d_in, const int* in_sizes, int n_in,
                              void* d_out, int out_size) {
    const float* x    = (const float*)d_in[0];   // (4, 2048, 512)
    const float* bias = (const float*)d_in[1];   // (4, 8, 2048, 2048)
    const float* Wq   = (const float*)d_in[2];   // (512, 512)
    const float* Wkv  = (const float*)d_in[3];   // (512, 1024)
    const float* Wo   = (const float*)d_in[4];   // (512, 512)
    const float* bo   = (const float*)d_in[5];   // (512,)
    float* out = (float*)d_out;                  // (4, 4, 512)

    k1_q<<<64, 256>>>(x, Wq);
    k2_qk<<<128, 256>>>(Wkv);
    k3_dots<<<128, 256>>>(x, bias);
    k5_part<<<128, 512>>>(x);
    k7_y<<<64, 256>>>(Wkv);
    k8_out<<<64, 256>>>(Wo, bo, out);
}

// round 14
// speedup vs baseline: 1.2679x; 1.0428x over previous
#include <cuda_runtime.h>

#define NB    4
#define NSEQ  2048
#define DIMV  512
#define NH    8
#define HD    64
#define NM    4
#define NROWS 16     // NB*NM
#define HM    32     // NH*NM
#define ASCALE 0.125f

// ---------------- scratch (device globals; no allocation allowed) ----------------
__device__ float g_q[NROWS * DIMV];
__device__ float g_qk[NB * HM * DIMV];
__device__ float g_dots[NB * HM * NSEQ];
__device__ float g_smax[NB * HM * 32];
__device__ float g_ssum[NB * HM * 32];
__device__ float g_ax[NB * HM * DIMV];

typedef unsigned long long u64;

__device__ __forceinline__ u64 fma2(u64 a, u64 b, u64 c) {
    u64 d; asm("fma.rn.f32x2 %0, %1, %2, %3;" : "=l"(d) : "l"(a), "l"(b), "l"(c)); return d;
}
__device__ __forceinline__ u64 pack2(float x, float y) {
    u64 r; asm("mov.b64 %0, {%1, %2};" : "=l"(r) : "f"(x), "f"(y)); return r;
}
__device__ __forceinline__ float2 unpack2(u64 v) {
    float2 f; asm("mov.b64 {%0, %1}, %2;" : "=f"(f.x), "=f"(f.y) : "l"(v)); return f;
}
__device__ __forceinline__ void redg4(float* p, float4 v) {
    asm volatile("red.global.add.v4.f32 [%0], {%1, %2, %3, %4};"
                 :: "l"(p), "f"(v.x), "f"(v.y), "f"(v.z), "f"(v.w) : "memory");
}
__device__ __forceinline__ void cpasync16(void* smem, const void* gmem) {
    unsigned saddr = (unsigned)__cvta_generic_to_shared(smem);
    asm volatile("cp.async.cg.shared.global [%0], [%1], 16;" :: "r"(saddr), "l"(gmem));
}
#define CP_COMMIT() asm volatile("cp.async.commit_group;")
#define CP_WAIT(n)  asm volatile("cp.async.wait_group %0;" :: "n"(n))

// ---------------- K1: q = x[:, 0:4] @ Wq  (16x512, k=512) ----------------
__global__ void k1_q(const float* __restrict__ x, const float* __restrict__ Wq) {
    __shared__ float A[NROWS * DIMV];
    int t = threadIdx.x;
    int c0 = blockIdx.x * 8;
    for (int i = t; i < NROWS * DIMV / 4; i += 256) {
        int r = i >> 7, k = (i & 127) << 2;
        *(float4*)&A[r * DIMV + k] =
            *(const float4*)&x[(size_t)(((r >> 2) * NSEQ) + (r & 3)) * DIMV + k];
    }
    __syncthreads();
    int cl = t & 7, kg = t >> 3;
    int c = c0 + cl;
    float acc[NROWS];
#pragma unroll
    for (int r = 0; r < NROWS; r++) acc[r] = 0.f;
    int k0 = kg << 4;
#pragma unroll
    for (int i = 0; i < 16; i++) {
        float w = Wq[(k0 + i) * DIMV + c];
#pragma unroll
        for (int r = 0; r < NROWS; r++) acc[r] += A[r * DIMV + k0 + i] * w;
    }
    __syncthreads();
#pragma unroll
    for (int r = 0; r < NROWS; r++) A[(kg << 7) + (r << 3) + cl] = acc[r];
    __syncthreads();
    if (t < 128) {
        int r = t >> 3, c2 = t & 7;
        float s = 0.f;
#pragma unroll
        for (int kg2 = 0; kg2 < 32; kg2++) s += A[(kg2 << 7) + (r << 3) + c2];
        g_q[r * DIMV + c0 + c2] = s;
    }
}

// ---------------- K2: qk + zero g_ax + init out = bo ----------------
__global__ void k2_qk(const float* __restrict__ Wkv, const float* __restrict__ bo,
                      float* __restrict__ out) {
    __shared__ float Ws[32][68];
    __shared__ float Qs[16][68];
    int t = threadIdx.x;
    int h = blockIdx.x >> 4, kc = blockIdx.x & 15;
    int kin0 = kc << 5;
#pragma unroll
    for (int i = 0; i < 2; i++) {
        int idx = t + (i << 8);
        int r = idx >> 4, c = (idx & 15) << 2;
        *(float4*)&Ws[r][c] =
            *(const float4*)&Wkv[(size_t)(kin0 + r) * (2 * DIMV) + h * HD + c];
    }
    {
        int r = t >> 4, c = (t & 15) << 2;
        *(float4*)&Qs[r][c] = *(const float4*)&g_q[r * DIMV + h * HD + c];
    }
    __syncthreads();
    int bm = t >> 4, kin = t & 15;
    float acc0 = 0.f, acc1 = 0.f;
#pragma unroll
    for (int dd = 0; dd < HD; dd += 4) {
        float4 q  = *(const float4*)&Qs[bm][dd];
        float4 w0 = *(const float4*)&Ws[kin][dd];
        float4 w1 = *(const float4*)&Ws[kin + 16][dd];
        acc0 += q.x * w0.x + q.y * w0.y + q.z * w0.z + q.w * w0.w;
        acc1 += q.x * w1.x + q.y * w1.y + q.z * w1.z + q.w * w1.w;
    }
    int b = bm >> 2, m = bm & 3;
    int hm = (h << 2) + m;
    g_qk[(b * HM + hm) * DIMV + kin0 + kin] = acc0;
    g_qk[(b * HM + hm) * DIMV + kin0 + kin + 16] = acc1;
    int zi = blockIdx.x * 256 + t;
    g_ax[zi] = 0.f;
    g_ax[zi + 32768] = 0.f;
    if (zi < NROWS * DIMV) out[zi] = bo[zi & (DIMV - 1)];   // out = bo (REDG base)
}

// ---------------- K3: dots = qk @ x^T * SCALE + bias + chunk stats ----------------
// grid 128 = (b, n-chunk 64). 256 thr. X double-buffered + register-pipelined LDG.
__global__ void k3_dots(const float* __restrict__ x, const float* __restrict__ bias) {
    __shared__ float QKs[64][34];
    __shared__ float Xs[2][64][68];
    int t = threadIdx.x;
    int b = blockIdx.x >> 5, nb = blockIdx.x & 31;
    int n0 = nb << 6;
    int tn = t & 15, th = t >> 4;
    int n4 = tn << 2, hm2 = th << 1;
    int l_hm = t >> 3, l_q8 = t & 7;
    int l_nn = t >> 2, l_q4 = t & 3;
    float4 qv[2], xv[4];

    u64 acc[2][2];
#pragma unroll
    for (int j = 0; j < 2; j++) { acc[j][0] = pack2(0.f, 0.f); acc[j][1] = pack2(0.f, 0.f); }

#define K3_LDG(dt)                                                                        \
    {   int d0_ = (dt) << 6;                                                              \
        _Pragma("unroll")                                                                 \
        for (int i = 0; i < 2; i++)                                                       \
            qv[i] = *(const float4*)&g_qk[(b * HM + l_hm) * DIMV + d0_ + ((l_q8 + (i << 3)) << 2)]; \
        _Pragma("unroll")                                                                 \
        for (int i = 0; i < 4; i++)                                                       \
            xv[i] = *(const float4*)&x[(size_t)(b * NSEQ + n0 + l_nn) * DIMV + d0_ + ((l_q4 + (i << 2)) << 2)]; \
    }
#define K3_STS_QK()                                                                       \
    {   _Pragma("unroll")                                                                 \
        for (int i = 0; i < 2; i++) {                                                     \
            int kk = (l_q8 + (i << 3)) << 2;                                              \
            QKs[kk][l_hm] = qv[i].x; QKs[kk + 1][l_hm] = qv[i].y;                         \
            QKs[kk + 2][l_hm] = qv[i].z; QKs[kk + 3][l_hm] = qv[i].w;                     \
        }                                                                                 \
    }
#define K3_STS_X(buf)                                                                     \
    {   _Pragma("unroll")                                                                 \
        for (int i = 0; i < 4; i++) {                                                     \
            int kk = (l_q4 + (i << 2)) << 2;                                              \
            Xs[buf][kk][l_nn] = xv[i].x; Xs[buf][kk + 1][l_nn] = xv[i].y;                 \
            Xs[buf][kk + 2][l_nn] = xv[i].z; Xs[buf][kk + 3][l_nn] = xv[i].w;             \
        }                                                                                 \
    }

    K3_LDG(0); K3_STS_QK(); K3_STS_X(0);
    K3_LDG(1);
    __syncthreads();
    for (int dt = 0; dt < 8; dt++) {
        int buf = dt & 1;
#pragma unroll
        for (int kk = 0; kk < 64; kk++) {
            float2 a = *(const float2*)&QKs[kk][hm2];
            ulonglong2 xx = *(const ulonglong2*)&Xs[buf][kk][n4];
            u64 a0 = pack2(a.x, a.x), a1 = pack2(a.y, a.y);
            acc[0][0] = fma2(a0, xx.x, acc[0][0]);
            acc[0][1] = fma2(a0, xx.y, acc[0][1]);
            acc[1][0] = fma2(a1, xx.x, acc[1][0]);
            acc[1][1] = fma2(a1, xx.y, acc[1][1]);
        }
        __syncthreads();
        if (dt < 7) {
            K3_STS_QK();
            K3_STS_X(1 - buf);
            if (dt + 2 < 8) K3_LDG(dt + 2);
            __syncthreads();
        }
    }
#pragma unroll
    for (int j = 0; j < 2; j++) {
        int hm = hm2 + j;
        int h = hm >> 2, m = hm & 3;
        float4 bv = *(const float4*)&bias[(size_t)((b * NH + h) * NSEQ + m) * NSEQ + n0 + n4];
        float2 p0 = unpack2(acc[j][0]);
        float2 p1 = unpack2(acc[j][1]);
        float4 o = make_float4(p0.x * ASCALE + bv.x, p0.y * ASCALE + bv.y,
                               p1.x * ASCALE + bv.z, p1.y * ASCALE + bv.w);
        *(float4*)&g_dots[(b * HM + hm) * NSEQ + n0 + n4] = o;
        float M = fmaxf(fmaxf(o.x, o.y), fmaxf(o.z, o.w));
#pragma unroll
        for (int off = 8; off; off >>= 1) M = fmaxf(M, __shfl_xor_sync(0xffffffffu, M, off));
        float s = __expf(o.x - M) + __expf(o.y - M) + __expf(o.z - M) + __expf(o.w - M);
#pragma unroll
        for (int off = 8; off; off >>= 1) s += __shfl_xor_sync(0xffffffffu, s, off);
        if (tn == 0) {
            g_smax[(b * HM + hm) * 32 + nb] = M;
            g_ssum[(b * HM + hm) * 32 + nb] = s;
        }
    }
}

// ---------------- K5: ax += softmax(dots) @ x  (8hm x 8d per thread, cp.async, REDG) ----------------
// grid 128 = (b, n-chunk 64 idx 0..31). 256 thr = 8 warps: 4 hm-groups(8) x 2 d-halves(256).
// Per nn: 2 As + 2 Xs LDS.128 -> 32 fma2 (LDS/FMA halved vs R11).
__global__ void __launch_bounds__(256) k5_part(const float* __restrict__ x) {
    __shared__ float As[64][36];
    __shared__ __align__(16) float Xs[2][8][520];
    __shared__ float sM[32], sInv[32];
    int t = threadIdx.x;
    int b = blockIdx.x >> 5, nc = blockIdx.x & 31;
    int n0 = nc << 6;
    int td = t & 31, wid = t >> 5;
    int hm8 = (wid & 3) << 3;          // hm-group of 8
    int dbase = (wid >> 2) << 8;       // 0 or 256
    // cp.async loader: 8 rows x 128 float4 per stage, 256 thr -> 4 each
    int c_nn = t >> 5, c_q = t & 31;

#define K5_ISSUE(s, buf)                                                                  \
    {   const float* gsrc = &x[(size_t)(b * NSEQ + n0 + ((s) << 3) + c_nn) * DIMV];       \
        _Pragma("unroll")                                                                 \
        for (int i = 0; i < 4; i++) {                                                     \
            int dd = (c_q + (i << 5)) << 2;                                               \
            cpasync16(&Xs[buf][c_nn][dd], gsrc + dd);                                     \
        }                                                                                 \
        CP_COMMIT();                                                                      \
    }

    K5_ISSUE(0, 0);
    K5_ISSUE(1, 1);
    // stats prologue: combine 32 chunk stats per row (overlaps async loads)
    {
        int row = t >> 3, j8 = t & 7;
        const float* pm = g_smax + (b * HM + row) * 32 + (j8 << 2);
        const float* ps = g_ssum + (b * HM + row) * 32 + (j8 << 2);
        float mv[4], sv[4];
        float M = -3.4e38f;
#pragma unroll
        for (int i = 0; i < 4; i++) { mv[i] = pm[i]; sv[i] = ps[i]; M = fmaxf(M, mv[i]); }
#pragma unroll
        for (int off = 4; off; off >>= 1) M = fmaxf(M, __shfl_xor_sync(0xffffffffu, M, off));
        float s = 0.f;
#pragma unroll
        for (int i = 0; i < 4; i++) s += __expf(mv[i] - M) * sv[i];
#pragma unroll
        for (int off = 4; off; off >>= 1) s += __shfl_xor_sync(0xffffffffu, s, off);
        if (j8 == 0) { sM[row] = M; sInv[row] = 1.f / s; }
    }
    __syncthreads();
    // As: 64n x 32hm transposed, exp applied (overlaps async loads)
    {
        int hm = t >> 3, q8 = t & 7;
        float M = sM[hm], is = sInv[hm];
#pragma unroll
        for (int i = 0; i < 2; i++) {
            int nn = (q8 + (i << 3)) << 2;
            float4 v = *(const float4*)&g_dots[(b * HM + hm) * NSEQ + n0 + nn];
            As[nn][hm]     = __expf(v.x - M) * is;
            As[nn + 1][hm] = __expf(v.y - M) * is;
            As[nn + 2][hm] = __expf(v.z - M) * is;
            As[nn + 3][hm] = __expf(v.w - M) * is;
        }
    }
    u64 acc[8][4];
#pragma unroll
    for (int j = 0; j < 8; j++)
#pragma unroll
        for (int k = 0; k < 4; k++) acc[j][k] = pack2(0.f, 0.f);

    for (int s = 0; s < 8; s++) {
        if (s < 7) { CP_WAIT(1); } else { CP_WAIT(0); }
        __syncthreads();
        int buf = s & 1;
#pragma unroll
        for (int nn2 = 0; nn2 < 8; nn2++) {
            int nn = (s << 3) + nn2;
            float4 aLo = *(const float4*)&As[nn][hm8];        // broadcast
            float4 aHi = *(const float4*)&As[nn][hm8 + 4];    // broadcast
            ulonglong2 x0 = *(const ulonglong2*)&Xs[buf][nn2][dbase + (td << 2)];
            ulonglong2 x1 = *(const ulonglong2*)&Xs[buf][nn2][dbase + 128 + (td << 2)];
            u64 a0 = pack2(aLo.x, aLo.x), a1 = pack2(aLo.y, aLo.y);
            u64 a2 = pack2(aLo.z, aLo.z), a3 = pack2(aLo.w, aLo.w);
            u64 a4 = pack2(aHi.x, aHi.x), a5 = pack2(aHi.y, aHi.y);
            u64 a6 = pack2(aHi.z, aHi.z), a7 = pack2(aHi.w, aHi.w);
            acc[0][0] = fma2(a0, x0.x, acc[0][0]); acc[0][1] = fma2(a0, x0.y, acc[0][1]);
            acc[0][2] = fma2(a0, x1.x, acc[0][2]); acc[0][3] = fma2(a0, x1.y, acc[0][3]);
            acc[1][0] = fma2(a1, x0.x, acc[1][0]); acc[1][1] = fma2(a1, x0.y, acc[1][1]);
            acc[1][2] = fma2(a1, x1.x, acc[1][2]); acc[1][3] = fma2(a1, x1.y, acc[1][3]);
            acc[2][0] = fma2(a2, x0.x, acc[2][0]); acc[2][1] = fma2(a2, x0.y, acc[2][1]);
            acc[2][2] = fma2(a2, x1.x, acc[2][2]); acc[2][3] = fma2(a2, x1.y, acc[2][3]);
            acc[3][0] = fma2(a3, x0.x, acc[3][0]); acc[3][1] = fma2(a3, x0.y, acc[3][1]);
            acc[3][2] = fma2(a3, x1.x, acc[3][2]); acc[3][3] = fma2(a3, x1.y, acc[3][3]);
            acc[4][0] = fma2(a4, x0.x, acc[4][0]); acc[4][1] = fma2(a4, x0.y, acc[4][1]);
            acc[4][2] = fma2(a4, x1.x, acc[4][2]); acc[4][3] = fma2(a4, x1.y, acc[4][3]);
            acc[5][0] = fma2(a5, x0.x, acc[5][0]); acc[5][1] = fma2(a5, x0.y, acc[5][1]);
            acc[5][2] = fma2(a5, x1.x, acc[5][2]); acc[5][3] = fma2(a5, x1.y, acc[5][3]);
            acc[6][0] = fma2(a6, x0.x, acc[6][0]); acc[6][1] = fma2(a6, x0.y, acc[6][1]);
            acc[6][2] = fma2(a6, x1.x, acc[6][2]); acc[6][3] = fma2(a6, x1.y, acc[6][3]);
            acc[7][0] = fma2(a7, x0.x, acc[7][0]); acc[7][1] = fma2(a7, x0.y, acc[7][1]);
            acc[7][2] = fma2(a7, x1.x, acc[7][2]); acc[7][3] = fma2(a7, x1.y, acc[7][3]);
        }
        __syncthreads();
        if (s + 2 < 8) { K5_ISSUE(s + 2, buf); }
    }
#pragma unroll
    for (int j = 0; j < 8; j++) {
        float* base = &g_ax[(size_t)(b * HM + hm8 + j) * DIMV + dbase];
        float2 p0 = unpack2(acc[j][0]), p1 = unpack2(acc[j][1]);
        redg4(base + (td << 2), make_float4(p0.x, p0.y, p1.x, p1.y));
        float2 p2 = unpack2(acc[j][2]), p3 = unpack2(acc[j][3]);
        redg4(base + 128 + (td << 2), make_float4(p2.x, p2.y, p3.x, p3.y));
    }
}

// ---------------- K78: out += (ax_h @ Wv[:, c0:c0+8]) @ Wo[c0:c0+8, :]  (fused) ----------------
// grid 64 (8 y-cols each). Phase 1 = old k7 into smem ys; phase 2 = rank-8 update REDG'd to out.
__global__ void k78(const float* __restrict__ Wkv, const float* __restrict__ Wo,
                    float* __restrict__ out) {
    __shared__ float A[NROWS * DIMV];
    __shared__ float ys[16][8];
    int t = threadIdx.x;
    int c0 = blockIdx.x * 8;
    int h = c0 >> 6;
    for (int i = t; i < NROWS * DIMV / 4; i += 256) {
        int r = i >> 7, k = (i & 127) << 2;
        *(float4*)&A[r * DIMV + k] =
            *(const float4*)&g_ax[(size_t)((((r >> 2) * NH + h) * NM) + (r & 3)) * DIMV + k];
    }
    __syncthreads();
    int cl = t & 7, kg = t >> 3;
    int c = c0 + cl;
    float acc[NROWS];
#pragma unroll
    for (int r = 0; r < NROWS; r++) acc[r] = 0.f;
    int k0 = kg << 4;
#pragma unroll
    for (int i = 0; i < 16; i++) {
        float w = Wkv[(size_t)(k0 + i) * (2 * DIMV) + DIMV + c];
#pragma unroll
        for (int r = 0; r < NROWS; r++) acc[r] += A[r * DIMV + k0 + i] * w;
    }
    __syncthreads();
#pragma unroll
    for (int r = 0; r < NROWS; r++) A[(kg << 7) + (r << 3) + cl] = acc[r];
    __syncthreads();
    if (t < 128) {
        int r = t >> 3, c2 = t & 7;
        float s = 0.f;
#pragma unroll
        for (int kg2 = 0; kg2 < 32; kg2++) s += A[(kg2 << 7) + (r << 3) + c2];
        ys[r][c2] = s;
    }
    __syncthreads();
    // phase 2: out[r, :] += ys[r, 0:8] @ Wo[c0:c0+8, :]
    {
        int r = t >> 4, oq = t & 15;
        float yv[8];
#pragma unroll
        for (int j = 0; j < 8; j++) yv[j] = ys[r][j];
#pragma unroll
        for (int i = 0; i < 8; i++) {
            int o = (oq + (i << 4)) << 2;
            float4 a = make_float4(0.f, 0.f, 0.f, 0.f);
#pragma unroll
            for (int j = 0; j < 8; j++) {
                float4 w = *(const float4*)&Wo[(size_t)(c0 + j) * DIMV + o];
                a.x += yv[j] * w.x; a.y += yv[j] * w.y;
                a.z += yv[j] * w.z; a.w += yv[j] * w.w;
            }
            redg4(&out[r * DIMV + o], a);
        }
    }
}

// ---------------- launch ----------------
extern "C" void kernel_launch(void* const* d_in, const int* in_sizes, int n_in,
                              void* d_out, int out_size) {
    const float* x    = (const float*)d_in[0];   // (4, 2048, 512)
    const float* bias = (const float*)d_in[1];   // (4, 8, 2048, 2048)
    const float* Wq   = (const float*)d_in[2];   // (512, 512)
    const float* Wkv  = (const float*)d_in[3];   // (512, 1024)
    const float* Wo   = (const float*)d_in[4];   // (512, 512)
    const float* bo   = (const float*)d_in[5];   // (512,)
    float* out = (float*)d_out;                  // (4, 4, 512)

    k1_q<<<64, 256>>>(x, Wq);
    k2_qk<<<128, 256>>>(Wkv, bo, out);
    k3_dots<<<128, 256>>>(x, bias);
    k5_part<<<128, 256>>>(x);
    k78<<<64, 256>>>(Wkv, Wo, out);
}